// round 1
// baseline (speedup 1.0000x reference)
#include <cuda_runtime.h>
#include <cuda_bf16.h>
#include <math.h>

// Problem constants: B=4, N=2048, DIM=1024, HEADS=16, DHEAD=64
#define SCALE 0.125f   // 64^-0.5

// Scratch (device globals — allocation-free rule)
__device__ float g_qkv[8192 * 3072];   // [row=8192][3072] : q | k | v, each [h*64+d]
__device__ float g_attn[8192 * 1024];  // attention output, row-major [b*2048+n][h*64+d]

// ---------------------------------------------------------------------------
// Tiled fp32 GEMM: C[M,N] = A[M,K] @ B[K,N] (+ bias). 128x128 tile, 8x8/thread.
// ---------------------------------------------------------------------------
#define GBM 128
#define GBN 128
#define GBK 8

__global__ __launch_bounds__(256, 2)
void gemm_kernel(const float* __restrict__ A, const float* __restrict__ B,
                 const float* __restrict__ bias, float* __restrict__ C,
                 int N, int K) {
    __shared__ float As[GBK][GBM + 4];
    __shared__ float Bs[GBK][GBN];

    int tid = threadIdx.x;
    int tx = tid & 15, ty = tid >> 4;
    int rowBase = blockIdx.y * GBM;
    int colBase = blockIdx.x * GBN;

    const float* Ap = A + (size_t)rowBase * K;
    const float* Bp = B + colBase;

    int aRow = tid >> 1;
    int aK   = (tid & 1) * 4;
    int bK   = tid >> 5;
    int bCol = (tid & 31) * 4;

    float acc[8][8];
#pragma unroll
    for (int i = 0; i < 8; i++)
#pragma unroll
        for (int j = 0; j < 8; j++) acc[i][j] = 0.f;

    float4 av = *(const float4*)(Ap + (size_t)aRow * K + aK);
    float4 bv = *(const float4*)(Bp + (size_t)bK * N + bCol);

    for (int k0 = 0; k0 < K; k0 += GBK) {
        As[aK + 0][aRow] = av.x;
        As[aK + 1][aRow] = av.y;
        As[aK + 2][aRow] = av.z;
        As[aK + 3][aRow] = av.w;
        *(float4*)&Bs[bK][bCol] = bv;
        __syncthreads();

        if (k0 + GBK < K) {  // prefetch next tile into registers
            av = *(const float4*)(Ap + (size_t)aRow * K + (k0 + GBK) + aK);
            bv = *(const float4*)(Bp + (size_t)(k0 + GBK + bK) * N + bCol);
        }

#pragma unroll
        for (int kk = 0; kk < GBK; kk++) {
            float a[8], b[8];
            *(float4*)&a[0] = *(const float4*)&As[kk][ty * 8];
            *(float4*)&a[4] = *(const float4*)&As[kk][ty * 8 + 4];
            *(float4*)&b[0] = *(const float4*)&Bs[kk][tx * 8];
            *(float4*)&b[4] = *(const float4*)&Bs[kk][tx * 8 + 4];
#pragma unroll
            for (int i = 0; i < 8; i++)
#pragma unroll
                for (int j = 0; j < 8; j++)
                    acc[i][j] = fmaf(a[i], b[j], acc[i][j]);
        }
        __syncthreads();
    }

#pragma unroll
    for (int i = 0; i < 8; i++) {
        int r = rowBase + ty * 8 + i;
        float* Cp = C + (size_t)r * N + colBase + tx * 8;
        float o[8];
#pragma unroll
        for (int j = 0; j < 8; j++) {
            float bb = bias ? bias[colBase + tx * 8 + j] : 0.f;
            o[j] = acc[i][j] + bb;
        }
        *(float4*)&Cp[0] = make_float4(o[0], o[1], o[2], o[3]);
        *(float4*)&Cp[4] = make_float4(o[4], o[5], o[6], o[7]);
    }
}

// ---------------------------------------------------------------------------
// Flash attention: one CTA = 64 query rows of one (b,h). Online softmax.
// Thread grid 16x16, each thread owns a 4x4 of (row, col/dim).
// ---------------------------------------------------------------------------
#define PADW 68                       // 68 floats/row: keeps float4 alignment, breaks bank stride
#define ATT_SMEM (4 * 64 * PADW * 4)  // Qs,Kt,Vs,Ss = 69632 bytes

__global__ __launch_bounds__(256, 2)
void attn_kernel(const float* __restrict__ qkv, float* __restrict__ out) {
    extern __shared__ float sm[];
    float* Qs = sm;                  // [qrow][d]
    float* Kt = sm + 64 * PADW;      // [d][krow]  (transposed)
    float* Vs = sm + 2 * 64 * PADW;  // [krow][d]
    float* Ss = sm + 3 * 64 * PADW;  // [qrow][krow] scores -> probs
    __shared__ float mrow[64], lrow[64], frow[64], red[64][4];

    int tid = threadIdx.x;
    int bh = blockIdx.x;             // 0..63
    int qt = blockIdx.y;             // 0..31
    int b = bh >> 4, h = bh & 15;

    const float* qbase = qkv + (size_t)(b * 2048 + qt * 64) * 3072 + h * 64;
    const float* kbase = qkv + (size_t)(b * 2048) * 3072 + 1024 + h * 64;
    const float* vbase = kbase + 1024;

    // Load Q tile [64][64]
#pragma unroll
    for (int i = 0; i < 4; i++) {
        int lin = tid + 256 * i;
        int row = lin >> 4;
        int d4  = (lin & 15) * 4;
        float4 v = *(const float4*)(qbase + (size_t)row * 3072 + d4);
        *(float4*)&Qs[row * PADW + d4] = v;
    }
    if (tid < 64) { mrow[tid] = -1e30f; lrow[tid] = 0.f; }

    int ty = tid >> 4, tx = tid & 15;
    int r0 = ty * 4;
    int c0 = tx * 4;     // key-col block for S, dim block for output
    int rr = tid >> 2, qq = tid & 3;

    float acc[4][4];
#pragma unroll
    for (int i = 0; i < 4; i++)
#pragma unroll
        for (int j = 0; j < 4; j++) acc[i][j] = 0.f;

    for (int kt = 0; kt < 32; kt++) {
        __syncthreads();  // protect smem reuse from previous iteration

        // Load K (transposed) and V tiles
#pragma unroll
        for (int i = 0; i < 4; i++) {
            int lin = tid + 256 * i;
            int row = lin >> 4;
            int d4  = (lin & 15) * 4;
            float4 kv = *(const float4*)(kbase + (size_t)(kt * 64 + row) * 3072 + d4);
            Kt[(d4 + 0) * PADW + row] = kv.x;
            Kt[(d4 + 1) * PADW + row] = kv.y;
            Kt[(d4 + 2) * PADW + row] = kv.z;
            Kt[(d4 + 3) * PADW + row] = kv.w;
            float4 vv = *(const float4*)(vbase + (size_t)(kt * 64 + row) * 3072 + d4);
            *(float4*)&Vs[row * PADW + d4] = vv;
        }
        __syncthreads();

        // S = Q @ K^T  (4x4 per thread)
        float s00 = 0.f, s01 = 0.f, s02 = 0.f, s03 = 0.f;
        float s10 = 0.f, s11 = 0.f, s12 = 0.f, s13 = 0.f;
        float s20 = 0.f, s21 = 0.f, s22 = 0.f, s23 = 0.f;
        float s30 = 0.f, s31 = 0.f, s32 = 0.f, s33 = 0.f;
#pragma unroll 8
        for (int k = 0; k < 64; k++) {
            float a0 = Qs[(r0 + 0) * PADW + k];
            float a1 = Qs[(r0 + 1) * PADW + k];
            float a2 = Qs[(r0 + 2) * PADW + k];
            float a3 = Qs[(r0 + 3) * PADW + k];
            float4 kb = *(const float4*)&Kt[k * PADW + c0];
            s00 = fmaf(a0, kb.x, s00); s01 = fmaf(a0, kb.y, s01);
            s02 = fmaf(a0, kb.z, s02); s03 = fmaf(a0, kb.w, s03);
            s10 = fmaf(a1, kb.x, s10); s11 = fmaf(a1, kb.y, s11);
            s12 = fmaf(a1, kb.z, s12); s13 = fmaf(a1, kb.w, s13);
            s20 = fmaf(a2, kb.x, s20); s21 = fmaf(a2, kb.y, s21);
            s22 = fmaf(a2, kb.z, s22); s23 = fmaf(a2, kb.w, s23);
            s30 = fmaf(a3, kb.x, s30); s31 = fmaf(a3, kb.y, s31);
            s32 = fmaf(a3, kb.z, s32); s33 = fmaf(a3, kb.w, s33);
        }
        *(float4*)&Ss[(r0 + 0) * PADW + c0] = make_float4(s00 * SCALE, s01 * SCALE, s02 * SCALE, s03 * SCALE);
        *(float4*)&Ss[(r0 + 1) * PADW + c0] = make_float4(s10 * SCALE, s11 * SCALE, s12 * SCALE, s13 * SCALE);
        *(float4*)&Ss[(r0 + 2) * PADW + c0] = make_float4(s20 * SCALE, s21 * SCALE, s22 * SCALE, s23 * SCALE);
        *(float4*)&Ss[(r0 + 3) * PADW + c0] = make_float4(s30 * SCALE, s31 * SCALE, s32 * SCALE, s33 * SCALE);
        __syncthreads();

        // Online softmax: 4 threads per row, 16 cols each
        float lmax = -1e30f;
#pragma unroll
        for (int c = 0; c < 16; c++)
            lmax = fmaxf(lmax, Ss[rr * PADW + qq * 16 + c]);
        red[rr][qq] = lmax;
        __syncthreads();
        float mold = mrow[rr];
        float mnew = fmaxf(fmaxf(fmaxf(red[rr][0], red[rr][1]),
                                 fmaxf(red[rr][2], red[rr][3])), mold);
        __syncthreads();
        float psum = 0.f;
#pragma unroll
        for (int c = 0; c < 16; c++) {
            float p = __expf(Ss[rr * PADW + qq * 16 + c] - mnew);
            Ss[rr * PADW + qq * 16 + c] = p;
            psum += p;
        }
        red[rr][qq] = psum;
        __syncthreads();
        if (qq == 0) {
            float factor = __expf(mold - mnew);
            lrow[rr] = lrow[rr] * factor + red[rr][0] + red[rr][1] + red[rr][2] + red[rr][3];
            mrow[rr] = mnew;
            frow[rr] = factor;
        }
        __syncthreads();

        // Rescale accumulator, then acc += P @ V
#pragma unroll
        for (int i = 0; i < 4; i++) {
            float f = frow[r0 + i];
#pragma unroll
            for (int j = 0; j < 4; j++) acc[i][j] *= f;
        }
#pragma unroll 8
        for (int c = 0; c < 64; c++) {
            float p0 = Ss[(r0 + 0) * PADW + c];
            float p1 = Ss[(r0 + 1) * PADW + c];
            float p2 = Ss[(r0 + 2) * PADW + c];
            float p3 = Ss[(r0 + 3) * PADW + c];
            float4 vv = *(const float4*)&Vs[c * PADW + c0];
            acc[0][0] = fmaf(p0, vv.x, acc[0][0]); acc[0][1] = fmaf(p0, vv.y, acc[0][1]);
            acc[0][2] = fmaf(p0, vv.z, acc[0][2]); acc[0][3] = fmaf(p0, vv.w, acc[0][3]);
            acc[1][0] = fmaf(p1, vv.x, acc[1][0]); acc[1][1] = fmaf(p1, vv.y, acc[1][1]);
            acc[1][2] = fmaf(p1, vv.z, acc[1][2]); acc[1][3] = fmaf(p1, vv.w, acc[1][3]);
            acc[2][0] = fmaf(p2, vv.x, acc[2][0]); acc[2][1] = fmaf(p2, vv.y, acc[2][1]);
            acc[2][2] = fmaf(p2, vv.z, acc[2][2]); acc[2][3] = fmaf(p2, vv.w, acc[2][3]);
            acc[3][0] = fmaf(p3, vv.x, acc[3][0]); acc[3][1] = fmaf(p3, vv.y, acc[3][1]);
            acc[3][2] = fmaf(p3, vv.z, acc[3][2]); acc[3][3] = fmaf(p3, vv.w, acc[3][3]);
        }
    }

    // Normalize and write out: [row][h*64 + d]
#pragma unroll
    for (int i = 0; i < 4; i++) {
        float inv = 1.f / lrow[r0 + i];
        int row = b * 2048 + qt * 64 + r0 + i;
        float4 o = make_float4(acc[i][0] * inv, acc[i][1] * inv,
                               acc[i][2] * inv, acc[i][3] * inv);
        *(float4*)&out[(size_t)row * 1024 + h * 64 + c0] = o;
    }
}

// ---------------------------------------------------------------------------
extern "C" void kernel_launch(void* const* d_in, const int* in_sizes, int n_in,
                              void* d_out, int out_size) {
    const float* x    = (const float*)d_in[0];   // [8192][1024]
    const float* Wqkv = (const float*)d_in[1];   // [1024][3072]
    const float* Wout = (const float*)d_in[2];   // [1024][1024]
    const float* bout = (const float*)d_in[3];   // [1024]
    float* out = (float*)d_out;                  // [8192][1024]

    float *qkv, *attn;
    cudaGetSymbolAddress((void**)&qkv, g_qkv);
    cudaGetSymbolAddress((void**)&attn, g_attn);

    cudaFuncSetAttribute(attn_kernel, cudaFuncAttributeMaxDynamicSharedMemorySize, ATT_SMEM);

    const int M = 8192;
    // 1) QKV projection
    gemm_kernel<<<dim3(3072 / GBN, M / GBM), 256>>>(x, Wqkv, nullptr, qkv, 3072, 1024);
    // 2) Attention (64 bh pairs x 32 q-tiles)
    attn_kernel<<<dim3(64, 32), 256, ATT_SMEM>>>(qkv, attn);
    // 3) Output projection + bias
    gemm_kernel<<<dim3(1024 / GBN, M / GBM), 256>>>(attn, Wout, bout, out, 1024, 1024);
}